// round 12
// baseline (speedup 1.0000x reference)
#include <cuda_runtime.h>
#include <cuda_bf16.h>
#include <cstdint>
#include <cstddef>

// ---------------------------------------------------------------------------
// Problem constants
// ---------------------------------------------------------------------------
#define NB   16
#define NH   64
#define NW   64
#define NC   512
#define NIC  64
#define NROWS (NB*NH*NW)          // 65536
#define LN_EPS 1e-3f

// Scratch (device globals = sanctioned no-alloc scratch)
__device__ float d_G [(size_t)NROWS * NIC];
__device__ float d_Hs[(size_t)NROWS * NIC];
__device__ __nv_bfloat16 d_Phi[(size_t)NROWS * NIC];
__device__ __nv_bfloat16 d_Plo[(size_t)NROWS * NIC];
// Pre-split K1 weights: [wf|wh] as [512][128] hi/lo
__device__ __nv_bfloat16 d_WH[512 * 128];
__device__ __nv_bfloat16 d_WL[512 * 128];
// K3 w_fgh pre-packed into m16n8k16 B-fragment layout, hi/lo planes:
// uint2 index = (n8*4 + ks)*32 + lane ; .x = b0 (k even pair), .y = b1 (k+8)
__device__ uint32_t d_FHf[16384];
__device__ uint32_t d_FLf[16384];

// ---------------------------------------------------------------------------
// Helpers (sm_80-family tensor path: mma.sync + ldmatrix + cp.async)
// ---------------------------------------------------------------------------
__device__ __forceinline__ uint32_t smem_u32(const void* p) {
    uint32_t a;
    asm("{ .reg .u64 t; cvta.to.shared.u64 t, %1; cvt.u32.u64 %0, t; }"
        : "=r"(a) : "l"(p));
    return a;
}
__device__ __forceinline__ void ldsm4(uint32_t r[4], uint32_t a) {
    asm volatile("ldmatrix.sync.aligned.m8n8.x4.shared.b16 {%0,%1,%2,%3}, [%4];"
                 : "=r"(r[0]), "=r"(r[1]), "=r"(r[2]), "=r"(r[3]) : "r"(a));
}
__device__ __forceinline__ void ldsm4t(uint32_t r[4], uint32_t a) {
    asm volatile("ldmatrix.sync.aligned.m8n8.x4.trans.shared.b16 {%0,%1,%2,%3}, [%4];"
                 : "=r"(r[0]), "=r"(r[1]), "=r"(r[2]), "=r"(r[3]) : "r"(a));
}
__device__ __forceinline__ void mma16816(float c[4], const uint32_t a[4],
                                         uint32_t b0, uint32_t b1) {
    asm volatile(
        "mma.sync.aligned.m16n8k16.row.col.f32.bf16.bf16.f32 "
        "{%0,%1,%2,%3}, {%4,%5,%6,%7}, {%8,%9}, {%0,%1,%2,%3};"
        : "+f"(c[0]), "+f"(c[1]), "+f"(c[2]), "+f"(c[3])
        : "r"(a[0]), "r"(a[1]), "r"(a[2]), "r"(a[3]), "r"(b0), "r"(b1));
}
__device__ __forceinline__ void hilo(float v, __nv_bfloat16& h, __nv_bfloat16& l) {
    h = __float2bfloat16(v);
    l = __float2bfloat16(v - __bfloat162float(h));
}
__device__ __forceinline__ void cp_a8(uint32_t s, const void* g) {
    asm volatile("cp.async.ca.shared.global [%0], [%1], 8;" :: "r"(s), "l"(g) : "memory");
}
__device__ __forceinline__ void cp_a16(uint32_t s, const void* g) {
    asm volatile("cp.async.cg.shared.global [%0], [%1], 16;" :: "r"(s), "l"(g) : "memory");
}
#define CP_COMMIT()  asm volatile("cp.async.commit_group;" ::: "memory")
#define CP_WAIT(n)   asm volatile("cp.async.wait_group %0;" :: "n"(n) : "memory")

// ---------------------------------------------------------------------------
// K0a: pre-split [wf|wh] to bf16 hi/lo (65536 elems).
// ---------------------------------------------------------------------------
__global__ __launch_bounds__(256)
void k0_prep(const float* __restrict__ wf, const float* __restrict__ wh)
{
    const int id = blockIdx.x * 256 + threadIdx.x;   // 0..65535
    const int k = id >> 7, n = id & 127;
    const float v = (n < NIC) ? wf[k * NIC + n] : wh[k * NIC + (n - NIC)];
    __nv_bfloat16 h, l; hilo(v, h, l);
    d_WH[id] = h; d_WL[id] = l;
}

// ---------------------------------------------------------------------------
// K0b: pack w_fgh hi/lo into B-fragment layout for K3's direct-LDG path.
// 8192 threads, one per (n8, ks, lane) fragment pair.
// ---------------------------------------------------------------------------
__global__ __launch_bounds__(256)
void k0b_frag(const float* __restrict__ wfgh)
{
    const int id   = blockIdx.x * 256 + threadIdx.x;  // 0..8191
    const int lane = id & 31;
    const int ks   = (id >> 5) & 3;
    const int n8   = id >> 7;                         // 0..63
    const int n    = n8 * 8 + (lane >> 2);
    const int kb   = ks * 16 + (lane & 3) * 2;

    __nv_bfloat16 h, l;
    uint32_t h00, h01, h10, h11, l00, l01, l10, l11;
    hilo(wfgh[(kb + 0) * NC + n], h, l); h00 = __bfloat16_as_ushort(h); l00 = __bfloat16_as_ushort(l);
    hilo(wfgh[(kb + 1) * NC + n], h, l); h01 = __bfloat16_as_ushort(h); l01 = __bfloat16_as_ushort(l);
    hilo(wfgh[(kb + 8) * NC + n], h, l); h10 = __bfloat16_as_ushort(h); l10 = __bfloat16_as_ushort(l);
    hilo(wfgh[(kb + 9) * NC + n], h, l); h11 = __bfloat16_as_ushort(h); l11 = __bfloat16_as_ushort(l);

    d_FHf[id * 2 + 0] = (h01 << 16) | h00;   // b0: low half = even k
    d_FHf[id * 2 + 1] = (h11 << 16) | h10;   // b1: k+8 pair
    d_FLf[id * 2 + 0] = (l01 << 16) | l00;
    d_FLf[id * 2 + 1] = (l11 << 16) | l10;
}

// ---------------------------------------------------------------------------
// K1 v4: identical to R11's K1 v3 but __launch_bounds__(512, 2):
// 64-reg budget -> 2 CTAs/SM (32 warps) for latency hiding.
// Dynamic smem 80896: buf0 0 / buf1 37888 (AH|AL|BH|BL) | red 75776 | gbuf 79872
// ---------------------------------------------------------------------------
#define K1_SMEM 80896
#define K1_BUF  37888
#define A_STR 40
#define B1_STR 136

__global__ __launch_bounds__(512, 2)
void k1_mma(const float* __restrict__ x,
            const float* __restrict__ gamma_f, const float* __restrict__ beta_f,
            const float* __restrict__ gamma_h, const float* __restrict__ beta_h)
{
    extern __shared__ char sm[];
    const uint32_t su = smem_u32(sm);
    const int AH = 0, AL = 10240, BH = 20480, BL = 29184;
    float (*red)[4][2] = reinterpret_cast<float (*)[4][2]>(sm + 75776);
    float* gbuf        = reinterpret_cast<float*>(sm + 79872);

    const int tid  = threadIdx.x;
    const int wid  = tid >> 5;
    const int lane = tid & 31;
    const int wm   = wid & 3;        // M warp-block (32 rows)
    const int wn   = wid >> 2;       // N warp-block (32 cols)
    const int row0 = blockIdx.x * 128;

    if (tid < 64) {
        gbuf[tid]       = gamma_f[tid];
        gbuf[64 + tid]  = beta_f[tid];
        gbuf[128 + tid] = gamma_h[tid];
        gbuf[192 + tid] = beta_h[tid];
    }

    float acc[2][4][4];
#pragma unroll
    for (int mi = 0; mi < 2; mi++)
#pragma unroll
        for (int ni = 0; ni < 4; ni++)
#pragma unroll
            for (int q = 0; q < 4; q++) acc[mi][ni][q] = 0.0f;

    float4 pa[2];

    // ---- prolog: A(0) regs + B(0) cp.async into buf0 ----
#pragma unroll
    for (int it = 0; it < 2; it++) {
        const int f4 = tid + it * 512;
        const int m  = f4 >> 3, kc = (f4 & 7) * 4;
        pa[it] = *reinterpret_cast<const float4*>(x + (size_t)(row0 + m) * NC + kc);
    }
#pragma unroll
    for (int it = 0; it < 2; it++) {
        const int f4 = tid + it * 512;
        const int k  = f4 >> 5, nc = (f4 & 31) * 4;
        cp_a8(su + BH + (k * B1_STR + nc) * 2, d_WH + k * 128 + nc);
        cp_a8(su + BL + (k * B1_STR + nc) * 2, d_WL + k * 128 + nc);
    }
    CP_COMMIT();

    for (int c = 0; c < 16; c++) {
        const int bo = (c & 1) * K1_BUF;

        // ---- STS A(c) with hi/lo convert ----
#pragma unroll
        for (int it = 0; it < 2; it++) {
            const int f4 = tid + it * 512;
            const int m  = f4 >> 3, kc = (f4 & 7) * 4;
            union { __nv_bfloat16 e[4]; uint2 u; } hh, ll;
            hilo(pa[it].x, hh.e[0], ll.e[0]);
            hilo(pa[it].y, hh.e[1], ll.e[1]);
            hilo(pa[it].z, hh.e[2], ll.e[2]);
            hilo(pa[it].w, hh.e[3], ll.e[3]);
            *reinterpret_cast<uint2*>(sm + bo + AH + (m * A_STR + kc) * 2) = hh.u;
            *reinterpret_cast<uint2*>(sm + bo + AL + (m * A_STR + kc) * 2) = ll.u;
        }
        CP_WAIT(0);          // B(c) landed
        __syncthreads();     // buf[c&1] visible; all warps done mma(c-1)

        if (c < 15) {        // prefetch chunk c+1 into the other buffer
            const int nbo = ((c + 1) & 1) * K1_BUF;
#pragma unroll
            for (int it = 0; it < 2; it++) {
                const int f4 = tid + it * 512;
                const int m  = f4 >> 3, kc = (f4 & 7) * 4;
                pa[it] = *reinterpret_cast<const float4*>(
                    x + (size_t)(row0 + m) * NC + (c + 1) * 32 + kc);
            }
#pragma unroll
            for (int it = 0; it < 2; it++) {
                const int f4 = tid + it * 512;
                const int k  = f4 >> 5, nc = (f4 & 31) * 4;
                cp_a8(su + nbo + BH + (k * B1_STR + nc) * 2,
                      d_WH + ((c + 1) * 32 + k) * 128 + nc);
                cp_a8(su + nbo + BL + (k * B1_STR + nc) * 2,
                      d_WL + ((c + 1) * 32 + k) * 128 + nc);
            }
            CP_COMMIT();
        }

        // ---- tensor math on buf[c&1] ----
#pragma unroll
        for (int ks = 0; ks < 32; ks += 16) {
            uint32_t ah[2][4], al_[2][4];
#pragma unroll
            for (int mi = 0; mi < 2; mi++) {
                const uint32_t off =
                    ((wm * 32 + mi * 16 + (lane & 15)) * A_STR + ks + (lane >> 4) * 8) * 2;
                ldsm4(ah[mi],  su + bo + AH + off);
                ldsm4(al_[mi], su + bo + AL + off);
            }
            uint32_t bh[2][4], bl[2][4];
#pragma unroll
            for (int p = 0; p < 2; p++) {
                const uint32_t off =
                    ((ks + (lane & 15)) * B1_STR + wn * 32 + p * 16 + (lane >> 4) * 8) * 2;
                ldsm4t(bh[p], su + bo + BH + off);
                ldsm4t(bl[p], su + bo + BL + off);
            }
#pragma unroll
            for (int mi = 0; mi < 2; mi++)
#pragma unroll
                for (int p = 0; p < 2; p++)
#pragma unroll
                    for (int ns = 0; ns < 2; ns++) {
                        const int ni = p * 2 + ns;
                        mma16816(acc[mi][ni], ah[mi],  bh[p][2 * ns], bh[p][2 * ns + 1]);
                        mma16816(acc[mi][ni], ah[mi],  bl[p][2 * ns], bl[p][2 * ns + 1]);
                        mma16816(acc[mi][ni], al_[mi], bh[p][2 * ns], bh[p][2 * ns + 1]);
                    }
        }
        // single sync per chunk: next STS targets the other buffer.
    }

    // ---- LN reduction direct from registers ----
#pragma unroll
    for (int mi = 0; mi < 2; mi++)
#pragma unroll
        for (int half = 0; half < 2; half++) {
            float s = 0.f, ss = 0.f;
#pragma unroll
            for (int ni = 0; ni < 4; ni++) {
                const float v0 = acc[mi][ni][half * 2];
                const float v1 = acc[mi][ni][half * 2 + 1];
                s += v0 + v1; ss += v0 * v0 + v1 * v1;
            }
#pragma unroll
            for (int o = 1; o < 4; o <<= 1) {
                s  += __shfl_xor_sync(0xffffffffu, s,  o);
                ss += __shfl_xor_sync(0xffffffffu, ss, o);
            }
            if ((lane & 3) == 0) {
                const int r = wm * 32 + mi * 16 + (lane >> 2) + half * 8;
                red[r][wn][0] = s;
                red[r][wn][1] = ss;
            }
        }
    __syncthreads();

    // ---- apply: combine 2 N-warps per 64-half, write d_G / d_Hs ----
    const int sel  = wn >> 1;
    const int base = sel * 2;
    float* dstB = sel ? d_Hs : d_G;
#pragma unroll
    for (int mi = 0; mi < 2; mi++)
#pragma unroll
        for (int half = 0; half < 2; half++) {
            const int r  = wm * 32 + mi * 16 + (lane >> 2) + half * 8;
            const float S  = red[r][base][0] + red[r][base + 1][0];
            const float SS = red[r][base][1] + red[r][base + 1][1];
            const float mean = S * (1.0f / NIC);
            const float inv  = rsqrtf(SS * (1.0f / NIC) - mean * mean + LN_EPS);
            float* dst = dstB + (size_t)(row0 + r) * NIC;
#pragma unroll
            for (int ni = 0; ni < 4; ni++) {
                const int col = (wn & 1) * 32 + ni * 8 + (lane & 3) * 2;
                const float g0 = gbuf[sel * 128 + col];
                const float g1 = gbuf[sel * 128 + col + 1];
                const float b0 = gbuf[sel * 128 + 64 + col];
                const float b1 = gbuf[sel * 128 + 64 + col + 1];
                float2 o;
                o.x = (acc[mi][ni][half * 2]     - mean) * inv * g0 + b0;
                o.y = (acc[mi][ni][half * 2 + 1] - mean) * inv * g1 + b1;
                *reinterpret_cast<float2*>(dst + col) = o;
            }
        }
}

// ---------------------------------------------------------------------------
// K2: P = softmax_h( G[b,w,h,i] * G[b,h,w,i] ) * H  -> bf16 hi/lo planes
// ---------------------------------------------------------------------------
__global__ __launch_bounds__(256)
void k2_softmax()
{
    __shared__ float red[4][64];
    const int tid = threadIdx.x;
    const int b   = blockIdx.x >> 6;
    const int w   = blockIdx.x & 63;
    const int i   = tid & 63;
    const int q   = tid >> 6;
    const int h0  = q * 16;

    float l[16];
#pragma unroll
    for (int hh = 0; hh < 16; hh++) {
        const int h = h0 + hh;
        const float gw = d_G[((size_t)((b * NH + w) * NW + h)) * NIC + i];
        const float gc = d_G[((size_t)((b * NH + h) * NW + w)) * NIC + i];
        l[hh] = gw * gc;
    }
    float m = l[0];
#pragma unroll
    for (int hh = 1; hh < 16; hh++) m = fmaxf(m, l[hh]);
    red[q][i] = m;
    __syncthreads();
    const float M = fmaxf(fmaxf(red[0][i], red[1][i]), fmaxf(red[2][i], red[3][i]));
    __syncthreads();

    float s = 0.0f;
#pragma unroll
    for (int hh = 0; hh < 16; hh++) {
        const float e = __expf(l[hh] - M);
        l[hh] = e;
        s += e;
    }
    red[q][i] = s;
    __syncthreads();
    const float S    = red[0][i] + red[1][i] + red[2][i] + red[3][i];
    const float rinv = 1.0f / S;

#pragma unroll
    for (int hh = 0; hh < 16; hh++) {
        const int h = h0 + hh;
        const size_t o = ((size_t)((b * NH + h) * NW + w)) * NIC + i;
        const float v = l[hh] * rinv * d_Hs[o];
        __nv_bfloat16 ph, pl; hilo(v, ph, pl);
        d_Phi[o] = ph;
        d_Plo[o] = pl;
    }
}

// ---------------------------------------------------------------------------
// K3 v5: B via fragment LDG from L2 (no B smem) -> smem 95232 -> 2 CTAs/SM.
// 512 threads (2 M-warps x 8 N-warps), 4 tiles/CTA, cp.async A double-buffer
// + smem-staged x residual (issued at mma start).
// smem: Abuf0 0 | Abuf1 11264 | x 22528 (32x520 f32) | red 89088 | gbuf 91136
// ---------------------------------------------------------------------------
#define K3_SMEM 95232
#define A3_STR 88
#define X_STR  520

__global__ __launch_bounds__(512, 2)
void k3_mma(const float* __restrict__ gamma, const float* __restrict__ beta,
            const float* __restrict__ scale,
            const float* __restrict__ x, float* __restrict__ out)
{
    extern __shared__ char sm[];
    const uint32_t su = smem_u32(sm);
    const int ABUF = 11264, XS = 22528;
    float (*red)[8][2] = reinterpret_cast<float (*)[8][2]>(sm + 89088);
    float* gbuf        = reinterpret_cast<float*>(sm + 91136);
    float* xsf         = reinterpret_cast<float*>(sm + XS);

    const uint2* FH = reinterpret_cast<const uint2*>(d_FHf);
    const uint2* FL = reinterpret_cast<const uint2*>(d_FLf);

    const int tid  = threadIdx.x;
    const int wid  = tid >> 5;
    const int lane = tid & 31;
    const int wn   = wid & 7;                // N warp-block (64 cols = 8 n8)
    const int wm2  = wid >> 3;               // M warp-block (16 rows)
    const float sc = scale[0];

    const int am = tid >> 4;                 // A-load row 0..31
    const int ak = (tid & 15) * 4;           // A-load k 0..60

    if (tid < 128) {
        *reinterpret_cast<float4*>(gbuf + tid * 4) =
            *reinterpret_cast<const float4*>(gamma + tid * 4);
        *reinterpret_cast<float4*>(gbuf + 512 + tid * 4) =
            *reinterpret_cast<const float4*>(beta + tid * 4);
    }
    // A tile 0
    {
        const int r0 = blockIdx.x * 4 * 32;
        const size_t go = (size_t)(r0 + am) * NIC + ak;
        cp_a8(su + (am * A3_STR + ak) * 2, d_Phi + go);
        cp_a8(su + 5632 + (am * A3_STR + ak) * 2, d_Plo + go);
    }
    CP_COMMIT();

    for (int t = 0; t < 4; t++) {
        const int row0 = (blockIdx.x * 4 + t) * 32;

        CP_WAIT(0);          // A(t) complete
        __syncthreads();     // A visible; epilogue(t-1) done -> x buf free

        // ---- issue x(t) into smem (hidden under mma below) ----
#pragma unroll
        for (int it = 0; it < 8; it++) {
            const int f  = tid + it * 512;   // 0..4095 float4
            const int r  = f >> 7;           // 0..31
            const int c4 = (f & 127) * 4;    // 0..508
            cp_a16(su + XS + (r * X_STR + c4) * 4,
                   x + (size_t)(row0 + r) * NC + c4);
        }
        CP_COMMIT();                          // group Gx

        if (t < 3) {                          // prefetch A(t+1), other buffer
            const int nb = ((t + 1) & 1) * ABUF;
            const size_t go = (size_t)(row0 + 32 + am) * NIC + ak;
            cp_a8(su + nb + (am * A3_STR + ak) * 2, d_Phi + go);
            cp_a8(su + nb + 5632 + (am * A3_STR + ak) * 2, d_Plo + go);
            CP_COMMIT();                      // group Ga
        }

        const int AHo = (t & 1) * ABUF;
        const int ALo = AHo + 5632;

        float acc[8][4];
#pragma unroll
        for (int ni = 0; ni < 8; ni++)
#pragma unroll
            for (int q = 0; q < 4; q++) acc[ni][q] = 0.0f;

#pragma unroll
        for (int ks = 0; ks < 4; ks++) {
            uint32_t ah[4], al_[4];
            {
                const uint32_t off =
                    ((wm2 * 16 + (lane & 15)) * A3_STR + ks * 16 + (lane >> 4) * 8) * 2;
                ldsm4(ah,  su + AHo + off);
                ldsm4(al_, su + ALo + off);
            }
            // B fragments straight from L2-hot packed arrays
            const int fbase = (wn * 8 * 4 + ks) * 32 + lane;
#pragma unroll
            for (int p8 = 0; p8 < 8; p8++) {
                const uint2 bh2 = __ldg(FH + fbase + p8 * 128);
                const uint2 bl2 = __ldg(FL + fbase + p8 * 128);
                mma16816(acc[p8], ah,  bh2.x, bh2.y);
                mma16816(acc[p8], ah,  bl2.x, bl2.y);
                mma16816(acc[p8], al_, bh2.x, bh2.y);
            }
        }

        // ---- LN reduction (quad shfl + 8-warp combine via red) ----
#pragma unroll
        for (int half = 0; half < 2; half++) {
            float s = 0.f, ss = 0.f;
#pragma unroll
            for (int ni = 0; ni < 8; ni++) {
                const float v0 = acc[ni][half * 2];
                const float v1 = acc[ni][half * 2 + 1];
                s += v0 + v1; ss += v0 * v0 + v1 * v1;
            }
#pragma unroll
            for (int o = 1; o < 4; o <<= 1) {
                s  += __shfl_xor_sync(0xffffffffu, s,  o);
                ss += __shfl_xor_sync(0xffffffffu, ss, o);
            }
            if ((lane & 3) == 0) {
                const int r = wm2 * 16 + (lane >> 2) + half * 8;
                red[r][wn][0] = s;
                red[r][wn][1] = ss;
            }
        }

        // x(t) long since arrived (hidden under mma); Ga may still fly (t<3)
        if (t < 3) { CP_WAIT(1); } else { CP_WAIT(0); }
        __syncthreads();     // red + x visible

        float mean[2], inv[2];
#pragma unroll
        for (int half = 0; half < 2; half++) {
            const int r = wm2 * 16 + (lane >> 2) + half * 8;
            float S = 0.f, SS = 0.f;
#pragma unroll
            for (int w8 = 0; w8 < 8; w8++) { S += red[r][w8][0]; SS += red[r][w8][1]; }
            const float m = S * (1.0f / NC);
            mean[half] = m;
            inv[half]  = rsqrtf(SS * (1.0f / NC) - m * m + LN_EPS);
        }

        // ---- apply + residual (x from smem), write out ----
#pragma unroll
        for (int ni = 0; ni < 8; ni++) {
            const int col = wn * 64 + ni * 8 + (lane & 3) * 2;
            const float g0 = gbuf[col],       g1 = gbuf[col + 1];
            const float b0 = gbuf[512 + col], b1 = gbuf[512 + col + 1];
#pragma unroll
            for (int half = 0; half < 2; half++) {
                const int rl = wm2 * 16 + (lane >> 2) + half * 8;
                const float2 x2 = *reinterpret_cast<const float2*>(
                    xsf + rl * X_STR + col);
                float2 o;
                o.x = x2.x + ((acc[ni][half * 2]     - mean[half]) * inv[half] * g0 + b0) * sc;
                o.y = x2.y + ((acc[ni][half * 2 + 1] - mean[half]) * inv[half] * g1 + b1) * sc;
                *reinterpret_cast<float2*>(out + (size_t)(row0 + rl) * NC + col) = o;
            }
        }
    }
}

// ---------------------------------------------------------------------------
// Launch. Inputs: 0:x 1:w_f 2:w_h 3:w_fgh 4:gamma_f 5:beta_f 6:gamma_h
// 7:beta_h 8:gamma_fgh 9:beta_fgh 10:scale
// ---------------------------------------------------------------------------
extern "C" void kernel_launch(void* const* d_in, const int* in_sizes, int n_in,
                              void* d_out, int out_size)
{
    (void)in_sizes; (void)n_in; (void)out_size;
    const float* x         = (const float*)d_in[0];
    const float* w_f       = (const float*)d_in[1];
    const float* w_h       = (const float*)d_in[2];
    const float* w_fgh     = (const float*)d_in[3];
    const float* gamma_f   = (const float*)d_in[4];
    const float* beta_f    = (const float*)d_in[5];
    const float* gamma_h   = (const float*)d_in[6];
    const float* beta_h    = (const float*)d_in[7];
    const float* gamma_fgh = (const float*)d_in[8];
    const float* beta_fgh  = (const float*)d_in[9];
    const float* scale     = (const float*)d_in[10];
    float* out             = (float*)d_out;

    cudaFuncSetAttribute(k1_mma, cudaFuncAttributeMaxDynamicSharedMemorySize, K1_SMEM);
    cudaFuncSetAttribute(k3_mma, cudaFuncAttributeMaxDynamicSharedMemorySize, K3_SMEM);

    k0_prep<<<256, 256>>>(w_f, w_h);
    k0b_frag<<<32, 256>>>(w_fgh);
    k1_mma<<<NROWS / 128, 512, K1_SMEM>>>(x, gamma_f, beta_f, gamma_h, beta_h);
    k2_softmax<<<NB * NW, 256>>>();
    k3_mma<<<NROWS / 128, 512, K3_SMEM>>>(gamma_fgh, beta_fgh, scale, x, out);
}

// round 13
// speedup vs baseline: 1.1274x; 1.1274x over previous
#include <cuda_runtime.h>
#include <cuda_bf16.h>
#include <cstdint>
#include <cstddef>

// ---------------------------------------------------------------------------
// Problem constants
// ---------------------------------------------------------------------------
#define NB   16
#define NH   64
#define NW   64
#define NC   512
#define NIC  64
#define NROWS (NB*NH*NW)          // 65536
#define LN_EPS 1e-3f

// Scratch (device globals = sanctioned no-alloc scratch)
__device__ float d_G [(size_t)NROWS * NIC];
__device__ float d_Hs[(size_t)NROWS * NIC];
__device__ __nv_bfloat16 d_Phi[(size_t)NROWS * NIC];
__device__ __nv_bfloat16 d_Plo[(size_t)NROWS * NIC];
// Pre-split weights: [wf|wh] as [512][128], w_fgh as [64][512]
__device__ __nv_bfloat16 d_WH[512 * 128];
__device__ __nv_bfloat16 d_WL[512 * 128];
__device__ __nv_bfloat16 d_FH[64 * 512];
__device__ __nv_bfloat16 d_FL[64 * 512];

// ---------------------------------------------------------------------------
// Helpers (sm_80-family tensor path: mma.sync + ldmatrix + cp.async)
// ---------------------------------------------------------------------------
__device__ __forceinline__ uint32_t smem_u32(const void* p) {
    uint32_t a;
    asm("{ .reg .u64 t; cvta.to.shared.u64 t, %1; cvt.u32.u64 %0, t; }"
        : "=r"(a) : "l"(p));
    return a;
}
__device__ __forceinline__ void ldsm4(uint32_t r[4], uint32_t a) {
    asm volatile("ldmatrix.sync.aligned.m8n8.x4.shared.b16 {%0,%1,%2,%3}, [%4];"
                 : "=r"(r[0]), "=r"(r[1]), "=r"(r[2]), "=r"(r[3]) : "r"(a));
}
__device__ __forceinline__ void ldsm4t(uint32_t r[4], uint32_t a) {
    asm volatile("ldmatrix.sync.aligned.m8n8.x4.trans.shared.b16 {%0,%1,%2,%3}, [%4];"
                 : "=r"(r[0]), "=r"(r[1]), "=r"(r[2]), "=r"(r[3]) : "r"(a));
}
__device__ __forceinline__ void mma16816(float c[4], const uint32_t a[4],
                                         uint32_t b0, uint32_t b1) {
    asm volatile(
        "mma.sync.aligned.m16n8k16.row.col.f32.bf16.bf16.f32 "
        "{%0,%1,%2,%3}, {%4,%5,%6,%7}, {%8,%9}, {%0,%1,%2,%3};"
        : "+f"(c[0]), "+f"(c[1]), "+f"(c[2]), "+f"(c[3])
        : "r"(a[0]), "r"(a[1]), "r"(a[2]), "r"(a[3]), "r"(b0), "r"(b1));
}
__device__ __forceinline__ void hilo(float v, __nv_bfloat16& h, __nv_bfloat16& l) {
    h = __float2bfloat16(v);
    l = __float2bfloat16(v - __bfloat162float(h));
}
__device__ __forceinline__ void cp_a8(uint32_t s, const void* g) {
    asm volatile("cp.async.ca.shared.global [%0], [%1], 8;" :: "r"(s), "l"(g) : "memory");
}
__device__ __forceinline__ void cp_a16(uint32_t s, const void* g) {
    asm volatile("cp.async.cg.shared.global [%0], [%1], 16;" :: "r"(s), "l"(g) : "memory");
}
#define CP_COMMIT()  asm volatile("cp.async.commit_group;" ::: "memory")
#define CP_WAIT(n)   asm volatile("cp.async.wait_group %0;" :: "n"(n) : "memory")

// ---------------------------------------------------------------------------
// K0: pre-split weights to bf16 hi/lo (98304 ids: 65536 W + 32768 F).
// ---------------------------------------------------------------------------
__global__ __launch_bounds__(256)
void k0_prep(const float* __restrict__ wf, const float* __restrict__ wh,
             const float* __restrict__ wfgh)
{
    const int id = blockIdx.x * 256 + threadIdx.x;
    if (id < 512 * 128) {
        const int k = id >> 7, n = id & 127;
        const float v = (n < NIC) ? wf[k * NIC + n] : wh[k * NIC + (n - NIC)];
        __nv_bfloat16 h, l; hilo(v, h, l);
        d_WH[id] = h; d_WL[id] = l;
    } else {
        const int id2 = id - 512 * 128;
        __nv_bfloat16 h, l; hilo(wfgh[id2], h, l);
        d_FH[id2] = h; d_FL[id2] = l;
    }
}

// ---------------------------------------------------------------------------
// K1 v3 (R11, best): 512 threads, 4x4 warp grid, 32x32 warp tiles,
// CTA 128x128, BK=32, double-buffered smem (one sync/chunk), B cp.async.
// Dynamic smem 80896: buf0 0 / buf1 37888 | red 75776 | gbuf 79872
// ---------------------------------------------------------------------------
#define K1_SMEM 80896
#define K1_BUF  37888
#define A_STR 40
#define B1_STR 136

__global__ __launch_bounds__(512, 1)
void k1_mma(const float* __restrict__ x,
            const float* __restrict__ gamma_f, const float* __restrict__ beta_f,
            const float* __restrict__ gamma_h, const float* __restrict__ beta_h)
{
    extern __shared__ char sm[];
    const uint32_t su = smem_u32(sm);
    const int AH = 0, AL = 10240, BH = 20480, BL = 29184;
    float (*red)[4][2] = reinterpret_cast<float (*)[4][2]>(sm + 75776);
    float* gbuf        = reinterpret_cast<float*>(sm + 79872);

    const int tid  = threadIdx.x;
    const int wid  = tid >> 5;
    const int lane = tid & 31;
    const int wm   = wid & 3;
    const int wn   = wid >> 2;
    const int row0 = blockIdx.x * 128;

    if (tid < 64) {
        gbuf[tid]       = gamma_f[tid];
        gbuf[64 + tid]  = beta_f[tid];
        gbuf[128 + tid] = gamma_h[tid];
        gbuf[192 + tid] = beta_h[tid];
    }

    float acc[2][4][4];
#pragma unroll
    for (int mi = 0; mi < 2; mi++)
#pragma unroll
        for (int ni = 0; ni < 4; ni++)
#pragma unroll
            for (int q = 0; q < 4; q++) acc[mi][ni][q] = 0.0f;

    float4 pa[2];

#pragma unroll
    for (int it = 0; it < 2; it++) {
        const int f4 = tid + it * 512;
        const int m  = f4 >> 3, kc = (f4 & 7) * 4;
        pa[it] = *reinterpret_cast<const float4*>(x + (size_t)(row0 + m) * NC + kc);
    }
#pragma unroll
    for (int it = 0; it < 2; it++) {
        const int f4 = tid + it * 512;
        const int k  = f4 >> 5, nc = (f4 & 31) * 4;
        cp_a8(su + BH + (k * B1_STR + nc) * 2, d_WH + k * 128 + nc);
        cp_a8(su + BL + (k * B1_STR + nc) * 2, d_WL + k * 128 + nc);
    }
    CP_COMMIT();

    for (int c = 0; c < 16; c++) {
        const int bo = (c & 1) * K1_BUF;

#pragma unroll
        for (int it = 0; it < 2; it++) {
            const int f4 = tid + it * 512;
            const int m  = f4 >> 3, kc = (f4 & 7) * 4;
            union { __nv_bfloat16 e[4]; uint2 u; } hh, ll;
            hilo(pa[it].x, hh.e[0], ll.e[0]);
            hilo(pa[it].y, hh.e[1], ll.e[1]);
            hilo(pa[it].z, hh.e[2], ll.e[2]);
            hilo(pa[it].w, hh.e[3], ll.e[3]);
            *reinterpret_cast<uint2*>(sm + bo + AH + (m * A_STR + kc) * 2) = hh.u;
            *reinterpret_cast<uint2*>(sm + bo + AL + (m * A_STR + kc) * 2) = ll.u;
        }
        CP_WAIT(0);
        __syncthreads();

        if (c < 15) {
            const int nbo = ((c + 1) & 1) * K1_BUF;
#pragma unroll
            for (int it = 0; it < 2; it++) {
                const int f4 = tid + it * 512;
                const int m  = f4 >> 3, kc = (f4 & 7) * 4;
                pa[it] = *reinterpret_cast<const float4*>(
                    x + (size_t)(row0 + m) * NC + (c + 1) * 32 + kc);
            }
#pragma unroll
            for (int it = 0; it < 2; it++) {
                const int f4 = tid + it * 512;
                const int k  = f4 >> 5, nc = (f4 & 31) * 4;
                cp_a8(su + nbo + BH + (k * B1_STR + nc) * 2,
                      d_WH + ((c + 1) * 32 + k) * 128 + nc);
                cp_a8(su + nbo + BL + (k * B1_STR + nc) * 2,
                      d_WL + ((c + 1) * 32 + k) * 128 + nc);
            }
            CP_COMMIT();
        }

#pragma unroll
        for (int ks = 0; ks < 32; ks += 16) {
            uint32_t ah[2][4], al_[2][4];
#pragma unroll
            for (int mi = 0; mi < 2; mi++) {
                const uint32_t off =
                    ((wm * 32 + mi * 16 + (lane & 15)) * A_STR + ks + (lane >> 4) * 8) * 2;
                ldsm4(ah[mi],  su + bo + AH + off);
                ldsm4(al_[mi], su + bo + AL + off);
            }
            uint32_t bh[2][4], bl[2][4];
#pragma unroll
            for (int p = 0; p < 2; p++) {
                const uint32_t off =
                    ((ks + (lane & 15)) * B1_STR + wn * 32 + p * 16 + (lane >> 4) * 8) * 2;
                ldsm4t(bh[p], su + bo + BH + off);
                ldsm4t(bl[p], su + bo + BL + off);
            }
#pragma unroll
            for (int mi = 0; mi < 2; mi++)
#pragma unroll
                for (int p = 0; p < 2; p++)
#pragma unroll
                    for (int ns = 0; ns < 2; ns++) {
                        const int ni = p * 2 + ns;
                        mma16816(acc[mi][ni], ah[mi],  bh[p][2 * ns], bh[p][2 * ns + 1]);
                        mma16816(acc[mi][ni], ah[mi],  bl[p][2 * ns], bl[p][2 * ns + 1]);
                        mma16816(acc[mi][ni], al_[mi], bh[p][2 * ns], bh[p][2 * ns + 1]);
                    }
        }
    }

#pragma unroll
    for (int mi = 0; mi < 2; mi++)
#pragma unroll
        for (int half = 0; half < 2; half++) {
            float s = 0.f, ss = 0.f;
#pragma unroll
            for (int ni = 0; ni < 4; ni++) {
                const float v0 = acc[mi][ni][half * 2];
                const float v1 = acc[mi][ni][half * 2 + 1];
                s += v0 + v1; ss += v0 * v0 + v1 * v1;
            }
#pragma unroll
            for (int o = 1; o < 4; o <<= 1) {
                s  += __shfl_xor_sync(0xffffffffu, s,  o);
                ss += __shfl_xor_sync(0xffffffffu, ss, o);
            }
            if ((lane & 3) == 0) {
                const int r = wm * 32 + mi * 16 + (lane >> 2) + half * 8;
                red[r][wn][0] = s;
                red[r][wn][1] = ss;
            }
        }
    __syncthreads();

    const int sel  = wn >> 1;
    const int base = sel * 2;
    float* dstB = sel ? d_Hs : d_G;
#pragma unroll
    for (int mi = 0; mi < 2; mi++)
#pragma unroll
        for (int half = 0; half < 2; half++) {
            const int r  = wm * 32 + mi * 16 + (lane >> 2) + half * 8;
            const float S  = red[r][base][0] + red[r][base + 1][0];
            const float SS = red[r][base][1] + red[r][base + 1][1];
            const float mean = S * (1.0f / NIC);
            const float inv  = rsqrtf(SS * (1.0f / NIC) - mean * mean + LN_EPS);
            float* dst = dstB + (size_t)(row0 + r) * NIC;
#pragma unroll
            for (int ni = 0; ni < 4; ni++) {
                const int col = (wn & 1) * 32 + ni * 8 + (lane & 3) * 2;
                const float g0 = gbuf[sel * 128 + col];
                const float g1 = gbuf[sel * 128 + col + 1];
                const float b0 = gbuf[sel * 128 + 64 + col];
                const float b1 = gbuf[sel * 128 + 64 + col + 1];
                float2 o;
                o.x = (acc[mi][ni][half * 2]     - mean) * inv * g0 + b0;
                o.y = (acc[mi][ni][half * 2 + 1] - mean) * inv * g1 + b1;
                *reinterpret_cast<float2*>(dst + col) = o;
            }
        }
}

// ---------------------------------------------------------------------------
// K2 v2: 1024 threads (32 warps), 4 h per thread — latency fix for the
// 39.5us profile (occ 22%, issue 12.6%). Same math, same layout.
// thread = (i = tid%64, q = tid/64 in 0..15), h = q*4..q*4+3.
// ---------------------------------------------------------------------------
__global__ __launch_bounds__(1024)
void k2_softmax()
{
    __shared__ float red[16][64];
    const int tid = threadIdx.x;
    const int b   = blockIdx.x >> 6;
    const int w   = blockIdx.x & 63;
    const int i   = tid & 63;
    const int q   = tid >> 6;        // 0..15
    const int h0  = q * 4;

    float l[4];
#pragma unroll
    for (int hh = 0; hh < 4; hh++) {
        const int h = h0 + hh;
        const float gw = d_G[((size_t)((b * NH + w) * NW + h)) * NIC + i]; // g[b,w,h,i]
        const float gc = d_G[((size_t)((b * NH + h) * NW + w)) * NIC + i]; // g[b,h,w,i]
        l[hh] = gw * gc;
    }
    float m = fmaxf(fmaxf(l[0], l[1]), fmaxf(l[2], l[3]));
    red[q][i] = m;
    __syncthreads();
    float M = red[0][i];
#pragma unroll
    for (int p = 1; p < 16; p++) M = fmaxf(M, red[p][i]);
    __syncthreads();

    float s = 0.0f;
#pragma unroll
    for (int hh = 0; hh < 4; hh++) {
        const float e = __expf(l[hh] - M);
        l[hh] = e;
        s += e;
    }
    red[q][i] = s;
    __syncthreads();
    float S = red[0][i];
#pragma unroll
    for (int p = 1; p < 16; p++) S += red[p][i];
    const float rinv = 1.0f / S;

#pragma unroll
    for (int hh = 0; hh < 4; hh++) {
        const int h = h0 + hh;
        const size_t o = ((size_t)((b * NH + h) * NW + w)) * NIC + i;
        const float v = l[hh] * rinv * d_Hs[o];
        __nv_bfloat16 ph, pl; hilo(v, ph, pl);
        d_Phi[o] = ph;
        d_Plo[o] = pl;
    }
}

// ---------------------------------------------------------------------------
// K3 v4 (R11, best): 512 threads (2 M-warps x 8 N-warps), B-resident,
// 4 tiles/CTA, cp.async A double-buffer + smem-staged x residual.
// smem: Abuf0 0 | Abuf1 11264 | BH 22528 | BL 89088 | x 155648 |
//       red 222208 | gbuf 224256  -> 228352 bytes
// ---------------------------------------------------------------------------
#define K3_SMEM 228352
#define A3_STR 88
#define B3_STR 520
#define X_STR  520

__global__ __launch_bounds__(512, 1)
void k3_mma(const float* __restrict__ gamma, const float* __restrict__ beta,
            const float* __restrict__ scale,
            const float* __restrict__ x, float* __restrict__ out)
{
    extern __shared__ char sm[];
    const uint32_t su = smem_u32(sm);
    const int ABUF = 11264;
    const int BH = 22528, BL = 89088, XS = 155648;
    float (*red)[8][2] = reinterpret_cast<float (*)[8][2]>(sm + 222208);
    float* gbuf        = reinterpret_cast<float*>(sm + 224256);
    float* xsf         = reinterpret_cast<float*>(sm + XS);

    const int tid  = threadIdx.x;
    const int wid  = tid >> 5;
    const int lane = tid & 31;
    const int wn   = wid & 7;
    const int wm2  = wid >> 3;
    const float sc = scale[0];

    const int am = tid >> 4;
    const int ak = (tid & 15) * 4;

    if (tid < 128) {
        *reinterpret_cast<float4*>(gbuf + tid * 4) =
            *reinterpret_cast<const float4*>(gamma + tid * 4);
        *reinterpret_cast<float4*>(gbuf + 512 + tid * 4) =
            *reinterpret_cast<const float4*>(beta + tid * 4);
    }
#pragma unroll
    for (int it = 0; it < 8; it++) {
        const int f  = tid + it * 512;
        const int k  = f >> 6;
        const int n8 = (f & 63) * 8;
        cp_a16(su + BH + (k * B3_STR + n8) * 2, d_FH + k * NC + n8);
        cp_a16(su + BL + (k * B3_STR + n8) * 2, d_FL + k * NC + n8);
    }
    {
        const int r0 = blockIdx.x * 4 * 32;
        const size_t go = (size_t)(r0 + am) * NIC + ak;
        cp_a8(su + (am * A3_STR + ak) * 2, d_Phi + go);
        cp_a8(su + 5632 + (am * A3_STR + ak) * 2, d_Plo + go);
    }
    CP_COMMIT();

    for (int t = 0; t < 4; t++) {
        const int row0 = (blockIdx.x * 4 + t) * 32;

        CP_WAIT(0);
        __syncthreads();

#pragma unroll
        for (int it = 0; it < 8; it++) {
            const int f  = tid + it * 512;
            const int r  = f >> 7;
            const int c4 = (f & 127) * 4;
            cp_a16(su + XS + (r * X_STR + c4) * 4,
                   x + (size_t)(row0 + r) * NC + c4);
        }
        CP_COMMIT();

        if (t < 3) {
            const int nb = ((t + 1) & 1) * ABUF;
            const size_t go = (size_t)(row0 + 32 + am) * NIC + ak;
            cp_a8(su + nb + (am * A3_STR + ak) * 2, d_Phi + go);
            cp_a8(su + nb + 5632 + (am * A3_STR + ak) * 2, d_Plo + go);
            CP_COMMIT();
        }

        const int AHo = (t & 1) * ABUF;
        const int ALo = AHo + 5632;

        float acc[8][4];
#pragma unroll
        for (int ni = 0; ni < 8; ni++)
#pragma unroll
            for (int q = 0; q < 4; q++) acc[ni][q] = 0.0f;

#pragma unroll
        for (int ks = 0; ks < 64; ks += 16) {
            uint32_t ah[4], al_[4];
            {
                const uint32_t off =
                    ((wm2 * 16 + (lane & 15)) * A3_STR + ks + (lane >> 4) * 8) * 2;
                ldsm4(ah,  su + AHo + off);
                ldsm4(al_, su + ALo + off);
            }
            uint32_t bh[4][4], bl[4][4];
#pragma unroll
            for (int p = 0; p < 4; p++) {
                const uint32_t off =
                    ((ks + (lane & 15)) * B3_STR + wn * 64 + p * 16 + (lane >> 4) * 8) * 2;
                ldsm4t(bh[p], su + BH + off);
                ldsm4t(bl[p], su + BL + off);
            }
#pragma unroll
            for (int p = 0; p < 4; p++)
#pragma unroll
                for (int ns = 0; ns < 2; ns++) {
                    const int ni = p * 2 + ns;
                    mma16816(acc[ni], ah,  bh[p][2 * ns], bh[p][2 * ns + 1]);
                    mma16816(acc[ni], ah,  bl[p][2 * ns], bl[p][2 * ns + 1]);
                    mma16816(acc[ni], al_, bh[p][2 * ns], bh[p][2 * ns + 1]);
                }
        }

#pragma unroll
        for (int half = 0; half < 2; half++) {
            float s = 0.f, ss = 0.f;
#pragma unroll
            for (int ni = 0; ni < 8; ni++) {
                const float v0 = acc[ni][half * 2];
                const float v1 = acc[ni][half * 2 + 1];
                s += v0 + v1; ss += v0 * v0 + v1 * v1;
            }
#pragma unroll
            for (int o = 1; o < 4; o <<= 1) {
                s  += __shfl_xor_sync(0xffffffffu, s,  o);
                ss += __shfl_xor_sync(0xffffffffu, ss, o);
            }
            if ((lane & 3) == 0) {
                const int r = wm2 * 16 + (lane >> 2) + half * 8;
                red[r][wn][0] = s;
                red[r][wn][1] = ss;
            }
        }

        if (t < 3) { CP_WAIT(1); } else { CP_WAIT(0); }
        __syncthreads();

        float mean[2], inv[2];
#pragma unroll
        for (int half = 0; half < 2; half++) {
            const int r = wm2 * 16 + (lane >> 2) + half * 8;
            float S = 0.f, SS = 0.f;
#pragma unroll
            for (int w8 = 0; w8 < 8; w8++) { S += red[r][w8][0]; SS += red[r][w8][1]; }
            const float m = S * (1.0f / NC);
            mean[half] = m;
            inv[half]  = rsqrtf(SS * (1.0f / NC) - m * m + LN_EPS);
        }

#pragma unroll
        for (int ni = 0; ni < 8; ni++) {
            const int col = wn * 64 + ni * 8 + (lane & 3) * 2;
            const float g0 = gbuf[col],       g1 = gbuf[col + 1];
            const float b0 = gbuf[512 + col], b1 = gbuf[512 + col + 1];
#pragma unroll
            for (int half = 0; half < 2; half++) {
                const int rl = wm2 * 16 + (lane >> 2) + half * 8;
                const float2 x2 = *reinterpret_cast<const float2*>(
                    xsf + rl * X_STR + col);
                float2 o;
                o.x = x2.x + ((acc[ni][half * 2]     - mean[half]) * inv[half] * g0 + b0) * sc;
                o.y = x2.y + ((acc[ni][half * 2 + 1] - mean[half]) * inv[half] * g1 + b1) * sc;
                *reinterpret_cast<float2*>(out + (size_t)(row0 + rl) * NC + col) = o;
            }
        }
    }
}

// ---------------------------------------------------------------------------
// Launch. Inputs: 0:x 1:w_f 2:w_h 3:w_fgh 4:gamma_f 5:beta_f 6:gamma_h
// 7:beta_h 8:gamma_fgh 9:beta_fgh 10:scale
// ---------------------------------------------------------------------------
extern "C" void kernel_launch(void* const* d_in, const int* in_sizes, int n_in,
                              void* d_out, int out_size)
{
    (void)in_sizes; (void)n_in; (void)out_size;
    const float* x         = (const float*)d_in[0];
    const float* w_f       = (const float*)d_in[1];
    const float* w_h       = (const float*)d_in[2];
    const float* w_fgh     = (const float*)d_in[3];
    const float* gamma_f   = (const float*)d_in[4];
    const float* beta_f    = (const float*)d_in[5];
    const float* gamma_h   = (const float*)d_in[6];
    const float* beta_h    = (const float*)d_in[7];
    const float* gamma_fgh = (const float*)d_in[8];
    const float* beta_fgh  = (const float*)d_in[9];
    const float* scale     = (const float*)d_in[10];
    float* out             = (float*)d_out;

    cudaFuncSetAttribute(k1_mma, cudaFuncAttributeMaxDynamicSharedMemorySize, K1_SMEM);
    cudaFuncSetAttribute(k3_mma, cudaFuncAttributeMaxDynamicSharedMemorySize, K3_SMEM);

    k0_prep<<<384, 256>>>(w_f, w_h, w_fgh);
    k1_mma<<<NROWS / 128, 512, K1_SMEM>>>(x, gamma_f, beta_f, gamma_h, beta_h);
    k2_softmax<<<NB * NW, 1024>>>();
    k3_mma<<<NROWS / 128, 512, K3_SMEM>>>(gamma_fgh, beta_fgh, scale, x, out);
}

// round 14
// speedup vs baseline: 1.2256x; 1.0871x over previous
#include <cuda_runtime.h>
#include <cuda_bf16.h>
#include <cstdint>
#include <cstddef>

// ---------------------------------------------------------------------------
// Problem constants
// ---------------------------------------------------------------------------
#define NB   16
#define NH   64
#define NW   64
#define NC   512
#define NIC  64
#define NROWS (NB*NH*NW)          // 65536
#define LN_EPS 1e-3f

// Scratch (device globals = sanctioned no-alloc scratch)
__device__ float d_G [(size_t)NROWS * NIC];
__device__ float d_Hs[(size_t)NROWS * NIC];
__device__ __nv_bfloat16 d_Phi[(size_t)NROWS * NIC];
__device__ __nv_bfloat16 d_Plo[(size_t)NROWS * NIC];
// Pre-split weights: [wf|wh] as [512][128], w_fgh as [64][512]
__device__ __nv_bfloat16 d_WH[512 * 128];
__device__ __nv_bfloat16 d_WL[512 * 128];
__device__ __nv_bfloat16 d_FH[64 * 512];
__device__ __nv_bfloat16 d_FL[64 * 512];

// ---------------------------------------------------------------------------
// Helpers (sm_80-family tensor path: mma.sync + ldmatrix + cp.async)
// ---------------------------------------------------------------------------
__device__ __forceinline__ uint32_t smem_u32(const void* p) {
    uint32_t a;
    asm("{ .reg .u64 t; cvta.to.shared.u64 t, %1; cvt.u32.u64 %0, t; }"
        : "=r"(a) : "l"(p));
    return a;
}
__device__ __forceinline__ void ldsm4(uint32_t r[4], uint32_t a) {
    asm volatile("ldmatrix.sync.aligned.m8n8.x4.shared.b16 {%0,%1,%2,%3}, [%4];"
                 : "=r"(r[0]), "=r"(r[1]), "=r"(r[2]), "=r"(r[3]) : "r"(a));
}
__device__ __forceinline__ void ldsm4t(uint32_t r[4], uint32_t a) {
    asm volatile("ldmatrix.sync.aligned.m8n8.x4.trans.shared.b16 {%0,%1,%2,%3}, [%4];"
                 : "=r"(r[0]), "=r"(r[1]), "=r"(r[2]), "=r"(r[3]) : "r"(a));
}
__device__ __forceinline__ void mma16816(float c[4], const uint32_t a[4],
                                         uint32_t b0, uint32_t b1) {
    asm volatile(
        "mma.sync.aligned.m16n8k16.row.col.f32.bf16.bf16.f32 "
        "{%0,%1,%2,%3}, {%4,%5,%6,%7}, {%8,%9}, {%0,%1,%2,%3};"
        : "+f"(c[0]), "+f"(c[1]), "+f"(c[2]), "+f"(c[3])
        : "r"(a[0]), "r"(a[1]), "r"(a[2]), "r"(a[3]), "r"(b0), "r"(b1));
}
__device__ __forceinline__ void hilo(float v, __nv_bfloat16& h, __nv_bfloat16& l) {
    h = __float2bfloat16(v);
    l = __float2bfloat16(v - __bfloat162float(h));
}
__device__ __forceinline__ void cp_a8(uint32_t s, const void* g) {
    asm volatile("cp.async.ca.shared.global [%0], [%1], 8;" :: "r"(s), "l"(g) : "memory");
}
__device__ __forceinline__ void cp_a16(uint32_t s, const void* g) {
    asm volatile("cp.async.cg.shared.global [%0], [%1], 16;" :: "r"(s), "l"(g) : "memory");
}
#define CP_COMMIT()  asm volatile("cp.async.commit_group;" ::: "memory")
#define CP_WAIT(n)   asm volatile("cp.async.wait_group %0;" :: "n"(n) : "memory")

// ---------------------------------------------------------------------------
// K0: pre-split weights to bf16 hi/lo (98304 ids: 65536 W + 32768 F).
// ---------------------------------------------------------------------------
__global__ __launch_bounds__(256)
void k0_prep(const float* __restrict__ wf, const float* __restrict__ wh,
             const float* __restrict__ wfgh)
{
    const int id = blockIdx.x * 256 + threadIdx.x;
    if (id < 512 * 128) {
        const int k = id >> 7, n = id & 127;
        const float v = (n < NIC) ? wf[k * NIC + n] : wh[k * NIC + (n - NIC)];
        __nv_bfloat16 h, l; hilo(v, h, l);
        d_WH[id] = h; d_WL[id] = l;
    } else {
        const int id2 = id - 512 * 128;
        __nv_bfloat16 h, l; hilo(wfgh[id2], h, l);
        d_FH[id2] = h; d_FL[id2] = l;
    }
}

// ---------------------------------------------------------------------------
// K1 v5: BK=64 chunks (8 chunks, half the syncs of v3), double-buffered,
// 512 threads, 4x4 warp grid, 32x32 warp tiles, CTA 128x128.
// Dynamic smem 148480:
//   buf0 0 / buf1 71680, each: AH 0(18432) | AL 18432 | BH 36864(17408) | BL 54272
//   red 143360 (128x4x2 f32) | gbuf 147456 (256 f32)
// ---------------------------------------------------------------------------
#define K1_SMEM 148480
#define K1_BUF  71680
#define A_STR 72      // 64 + 8 pad (bf16 elems)
#define B1_STR 136

__global__ __launch_bounds__(512, 1)
void k1_mma(const float* __restrict__ x,
            const float* __restrict__ gamma_f, const float* __restrict__ beta_f,
            const float* __restrict__ gamma_h, const float* __restrict__ beta_h)
{
    extern __shared__ char sm[];
    const uint32_t su = smem_u32(sm);
    const int AH = 0, AL = 18432, BH = 36864, BL = 54272;
    float (*red)[4][2] = reinterpret_cast<float (*)[4][2]>(sm + 143360);
    float* gbuf        = reinterpret_cast<float*>(sm + 147456);

    const int tid  = threadIdx.x;
    const int wid  = tid >> 5;
    const int lane = tid & 31;
    const int wm   = wid & 3;        // M warp-block (32 rows)
    const int wn   = wid >> 2;       // N warp-block (32 cols)
    const int row0 = blockIdx.x * 128;

    if (tid < 64) {
        gbuf[tid]       = gamma_f[tid];
        gbuf[64 + tid]  = beta_f[tid];
        gbuf[128 + tid] = gamma_h[tid];
        gbuf[192 + tid] = beta_h[tid];
    }

    float acc[2][4][4];
#pragma unroll
    for (int mi = 0; mi < 2; mi++)
#pragma unroll
        for (int ni = 0; ni < 4; ni++)
#pragma unroll
            for (int q = 0; q < 4; q++) acc[mi][ni][q] = 0.0f;

    float4 pa[4];

    // ---- prolog: A(0) regs + B(0) cp.async into buf0 ----
#pragma unroll
    for (int it = 0; it < 4; it++) {
        const int f4 = tid + it * 512;           // 0..2047
        const int m  = f4 >> 4, kc = (f4 & 15) * 4;
        pa[it] = *reinterpret_cast<const float4*>(x + (size_t)(row0 + m) * NC + kc);
    }
#pragma unroll
    for (int it = 0; it < 4; it++) {
        const int f  = tid + it * 512;           // 0..2047
        const int k  = f >> 5, nc = (f & 31) * 4;   // k 0..63
        cp_a8(su + BH + (k * B1_STR + nc) * 2, d_WH + k * 128 + nc);
        cp_a8(su + BL + (k * B1_STR + nc) * 2, d_WL + k * 128 + nc);
    }
    CP_COMMIT();

    for (int c = 0; c < 8; c++) {
        const int bo = (c & 1) * K1_BUF;

        // ---- STS A(c) with hi/lo convert ----
#pragma unroll
        for (int it = 0; it < 4; it++) {
            const int f4 = tid + it * 512;
            const int m  = f4 >> 4, kc = (f4 & 15) * 4;
            union { __nv_bfloat16 e[4]; uint2 u; } hh, ll;
            hilo(pa[it].x, hh.e[0], ll.e[0]);
            hilo(pa[it].y, hh.e[1], ll.e[1]);
            hilo(pa[it].z, hh.e[2], ll.e[2]);
            hilo(pa[it].w, hh.e[3], ll.e[3]);
            *reinterpret_cast<uint2*>(sm + bo + AH + (m * A_STR + kc) * 2) = hh.u;
            *reinterpret_cast<uint2*>(sm + bo + AL + (m * A_STR + kc) * 2) = ll.u;
        }
        CP_WAIT(0);          // B(c) landed
        __syncthreads();     // buf[c&1] visible; all warps done mma(c-1)

        if (c < 7) {         // prefetch chunk c+1 into the other buffer
            const int nbo = ((c + 1) & 1) * K1_BUF;
#pragma unroll
            for (int it = 0; it < 4; it++) {
                const int f4 = tid + it * 512;
                const int m  = f4 >> 4, kc = (f4 & 15) * 4;
                pa[it] = *reinterpret_cast<const float4*>(
                    x + (size_t)(row0 + m) * NC + (c + 1) * 64 + kc);
            }
#pragma unroll
            for (int it = 0; it < 4; it++) {
                const int f  = tid + it * 512;
                const int k  = f >> 5, nc = (f & 31) * 4;
                cp_a8(su + nbo + BH + (k * B1_STR + nc) * 2,
                      d_WH + ((c + 1) * 64 + k) * 128 + nc);
                cp_a8(su + nbo + BL + (k * B1_STR + nc) * 2,
                      d_WL + ((c + 1) * 64 + k) * 128 + nc);
            }
            CP_COMMIT();
        }

        // ---- tensor math on buf[c&1], K=64 ----
#pragma unroll
        for (int ks = 0; ks < 64; ks += 16) {
            uint32_t ah[2][4], al_[2][4];
#pragma unroll
            for (int mi = 0; mi < 2; mi++) {
                const uint32_t off =
                    ((wm * 32 + mi * 16 + (lane & 15)) * A_STR + ks + (lane >> 4) * 8) * 2;
                ldsm4(ah[mi],  su + bo + AH + off);
                ldsm4(al_[mi], su + bo + AL + off);
            }
            uint32_t bh[2][4], bl[2][4];
#pragma unroll
            for (int p = 0; p < 2; p++) {
                const uint32_t off =
                    ((ks + (lane & 15)) * B1_STR + wn * 32 + p * 16 + (lane >> 4) * 8) * 2;
                ldsm4t(bh[p], su + bo + BH + off);
                ldsm4t(bl[p], su + bo + BL + off);
            }
#pragma unroll
            for (int mi = 0; mi < 2; mi++)
#pragma unroll
                for (int p = 0; p < 2; p++)
#pragma unroll
                    for (int ns = 0; ns < 2; ns++) {
                        const int ni = p * 2 + ns;
                        mma16816(acc[mi][ni], ah[mi],  bh[p][2 * ns], bh[p][2 * ns + 1]);
                        mma16816(acc[mi][ni], ah[mi],  bl[p][2 * ns], bl[p][2 * ns + 1]);
                        mma16816(acc[mi][ni], al_[mi], bh[p][2 * ns], bh[p][2 * ns + 1]);
                    }
        }
        // single sync per chunk: next STS targets the other buffer.
    }

    // ---- LN reduction direct from registers ----
#pragma unroll
    for (int mi = 0; mi < 2; mi++)
#pragma unroll
        for (int half = 0; half < 2; half++) {
            float s = 0.f, ss = 0.f;
#pragma unroll
            for (int ni = 0; ni < 4; ni++) {
                const float v0 = acc[mi][ni][half * 2];
                const float v1 = acc[mi][ni][half * 2 + 1];
                s += v0 + v1; ss += v0 * v0 + v1 * v1;
            }
#pragma unroll
            for (int o = 1; o < 4; o <<= 1) {
                s  += __shfl_xor_sync(0xffffffffu, s,  o);
                ss += __shfl_xor_sync(0xffffffffu, ss, o);
            }
            if ((lane & 3) == 0) {
                const int r = wm * 32 + mi * 16 + (lane >> 2) + half * 8;
                red[r][wn][0] = s;
                red[r][wn][1] = ss;
            }
        }
    __syncthreads();

    // ---- apply: combine 2 N-warps per 64-half, write d_G / d_Hs ----
    const int sel  = wn >> 1;
    const int base = sel * 2;
    float* dstB = sel ? d_Hs : d_G;
#pragma unroll
    for (int mi = 0; mi < 2; mi++)
#pragma unroll
        for (int half = 0; half < 2; half++) {
            const int r  = wm * 32 + mi * 16 + (lane >> 2) + half * 8;
            const float S  = red[r][base][0] + red[r][base + 1][0];
            const float SS = red[r][base][1] + red[r][base + 1][1];
            const float mean = S * (1.0f / NIC);
            const float inv  = rsqrtf(SS * (1.0f / NIC) - mean * mean + LN_EPS);
            float* dst = dstB + (size_t)(row0 + r) * NIC;
#pragma unroll
            for (int ni = 0; ni < 4; ni++) {
                const int col = (wn & 1) * 32 + ni * 8 + (lane & 3) * 2;
                const float g0 = gbuf[sel * 128 + col];
                const float g1 = gbuf[sel * 128 + col + 1];
                const float b0 = gbuf[sel * 128 + 64 + col];
                const float b1 = gbuf[sel * 128 + 64 + col + 1];
                float2 o;
                o.x = (acc[mi][ni][half * 2]     - mean) * inv * g0 + b0;
                o.y = (acc[mi][ni][half * 2 + 1] - mean) * inv * g1 + b1;
                *reinterpret_cast<float2*>(dst + col) = o;
            }
        }
}

// ---------------------------------------------------------------------------
// K2 v2: 1024 threads, 4 h per thread (R13, good).
// ---------------------------------------------------------------------------
__global__ __launch_bounds__(1024)
void k2_softmax()
{
    __shared__ float red[16][64];
    const int tid = threadIdx.x;
    const int b   = blockIdx.x >> 6;
    const int w   = blockIdx.x & 63;
    const int i   = tid & 63;
    const int q   = tid >> 6;        // 0..15
    const int h0  = q * 4;

    float l[4];
#pragma unroll
    for (int hh = 0; hh < 4; hh++) {
        const int h = h0 + hh;
        const float gw = d_G[((size_t)((b * NH + w) * NW + h)) * NIC + i];
        const float gc = d_G[((size_t)((b * NH + h) * NW + w)) * NIC + i];
        l[hh] = gw * gc;
    }
    float m = fmaxf(fmaxf(l[0], l[1]), fmaxf(l[2], l[3]));
    red[q][i] = m;
    __syncthreads();
    float M = red[0][i];
#pragma unroll
    for (int p = 1; p < 16; p++) M = fmaxf(M, red[p][i]);
    __syncthreads();

    float s = 0.0f;
#pragma unroll
    for (int hh = 0; hh < 4; hh++) {
        const float e = __expf(l[hh] - M);
        l[hh] = e;
        s += e;
    }
    red[q][i] = s;
    __syncthreads();
    float S = red[0][i];
#pragma unroll
    for (int p = 1; p < 16; p++) S += red[p][i];
    const float rinv = 1.0f / S;

#pragma unroll
    for (int hh = 0; hh < 4; hh++) {
        const int h = h0 + hh;
        const size_t o = ((size_t)((b * NH + h) * NW + w)) * NIC + i;
        const float v = l[hh] * rinv * d_Hs[o];
        __nv_bfloat16 ph, pl; hilo(v, ph, pl);
        d_Phi[o] = ph;
        d_Plo[o] = pl;
    }
}

// ---------------------------------------------------------------------------
// K3 v6: PERSISTENT (grid 148, 1 CTA/SM): CTA strides over the 2048 32-row
// tiles -> ~13.8 tiles/CTA, tail waste ~1% (vs ~13% at grid 512).
// B-resident, cp.async A double-buffer + smem-staged x residual.
// smem: Abuf0 0 | Abuf1 11264 | BH 22528 | BL 89088 | x 155648 |
//       red 222208 | gbuf 224256  -> 228352 bytes
// ---------------------------------------------------------------------------
#define K3_SMEM 228352
#define K3_GRID 148
#define K3_NT   (NROWS / 32)     // 2048 tiles
#define A3_STR 88
#define B3_STR 520
#define X_STR  520

__global__ __launch_bounds__(512, 1)
void k3_mma(const float* __restrict__ gamma, const float* __restrict__ beta,
            const float* __restrict__ scale,
            const float* __restrict__ x, float* __restrict__ out)
{
    extern __shared__ char sm[];
    const uint32_t su = smem_u32(sm);
    const int ABUF = 11264;
    const int BH = 22528, BL = 89088, XS = 155648;
    float (*red)[8][2] = reinterpret_cast<float (*)[8][2]>(sm + 222208);
    float* gbuf        = reinterpret_cast<float*>(sm + 224256);
    float* xsf         = reinterpret_cast<float*>(sm + XS);

    const int tid  = threadIdx.x;
    const int wid  = tid >> 5;
    const int lane = tid & 31;
    const int wn   = wid & 7;
    const int wm2  = wid >> 3;
    const float sc = scale[0];

    const int am = tid >> 4;
    const int ak = (tid & 15) * 4;

    if (tid < 128) {
        *reinterpret_cast<float4*>(gbuf + tid * 4) =
            *reinterpret_cast<const float4*>(gamma + tid * 4);
        *reinterpret_cast<float4*>(gbuf + 512 + tid * 4) =
            *reinterpret_cast<const float4*>(beta + tid * 4);
    }
    // B (one-time) + A(first tile), single group
#pragma unroll
    for (int it = 0; it < 8; it++) {
        const int f  = tid + it * 512;
        const int k  = f >> 6;
        const int n8 = (f & 63) * 8;
        cp_a16(su + BH + (k * B3_STR + n8) * 2, d_FH + k * NC + n8);
        cp_a16(su + BL + (k * B3_STR + n8) * 2, d_FL + k * NC + n8);
    }
    {
        const size_t go = (size_t)(blockIdx.x * 32 + am) * NIC + ak;
        cp_a8(su + (am * A3_STR + ak) * 2, d_Phi + go);
        cp_a8(su + 5632 + (am * A3_STR + ak) * 2, d_Plo + go);
    }
    CP_COMMIT();

    int itc = 0;   // iteration counter -> A buffer parity
    for (int t = blockIdx.x; t < K3_NT; t += K3_GRID, itc++) {
        const int row0 = t * 32;
        const bool hasnext = (t + K3_GRID) < K3_NT;

        CP_WAIT(0);          // A(t) complete (and B on first iter)
        __syncthreads();     // A visible; epilogue(prev) done -> x buf free

        // ---- issue x(t) into smem (hidden under mma below) ----
#pragma unroll
        for (int it = 0; it < 8; it++) {
            const int f  = tid + it * 512;
            const int r  = f >> 7;
            const int c4 = (f & 127) * 4;
            cp_a16(su + XS + (r * X_STR + c4) * 4,
                   x + (size_t)(row0 + r) * NC + c4);
        }
        CP_COMMIT();                          // group Gx

        if (hasnext) {                        // prefetch A(next), other buffer
            const int nb = ((itc + 1) & 1) * ABUF;
            const size_t go = (size_t)((t + K3_GRID) * 32 + am) * NIC + ak;
            cp_a8(su + nb + (am * A3_STR + ak) * 2, d_Phi + go);
            cp_a8(su + nb + 5632 + (am * A3_STR + ak) * 2, d_Plo + go);
            CP_COMMIT();                      // group Ga
        }

        const int AHo = (itc & 1) * ABUF;
        const int ALo = AHo + 5632;

        float acc[8][4];
#pragma unroll
        for (int ni = 0; ni < 8; ni++)
#pragma unroll
            for (int q = 0; q < 4; q++) acc[ni][q] = 0.0f;

#pragma unroll
        for (int ks = 0; ks < 64; ks += 16) {
            uint32_t ah[4], al_[4];
            {
                const uint32_t off =
                    ((wm2 * 16 + (lane & 15)) * A3_STR + ks + (lane >> 4) * 8) * 2;
                ldsm4(ah,  su + AHo + off);
                ldsm4(al_, su + ALo + off);
            }
            uint32_t bh[4][4], bl[4][4];
#pragma unroll
            for (int p = 0; p < 4; p++) {
                const uint32_t off =
                    ((ks + (lane & 15)) * B3_STR + wn * 64 + p * 16 + (lane >> 4) * 8) * 2;
                ldsm4t(bh[p], su + BH + off);
                ldsm4t(bl[p], su + BL + off);
            }
#pragma unroll
            for (int p = 0; p < 4; p++)
#pragma unroll
                for (int ns = 0; ns < 2; ns++) {
                    const int ni = p * 2 + ns;
                    mma16816(acc[ni], ah,  bh[p][2 * ns], bh[p][2 * ns + 1]);
                    mma16816(acc[ni], ah,  bl[p][2 * ns], bl[p][2 * ns + 1]);
                    mma16816(acc[ni], al_, bh[p][2 * ns], bh[p][2 * ns + 1]);
                }
        }

        // ---- LN reduction (quad shfl + 8-warp combine via red) ----
#pragma unroll
        for (int half = 0; half < 2; half++) {
            float s = 0.f, ss = 0.f;
#pragma unroll
            for (int ni = 0; ni < 8; ni++) {
                const float v0 = acc[ni][half * 2];
                const float v1 = acc[ni][half * 2 + 1];
                s += v0 + v1; ss += v0 * v0 + v1 * v1;
            }
#pragma unroll
            for (int o = 1; o < 4; o <<= 1) {
                s  += __shfl_xor_sync(0xffffffffu, s,  o);
                ss += __shfl_xor_sync(0xffffffffu, ss, o);
            }
            if ((lane & 3) == 0) {
                const int r = wm2 * 16 + (lane >> 2) + half * 8;
                red[r][wn][0] = s;
                red[r][wn][1] = ss;
            }
        }

        if (hasnext) { CP_WAIT(1); } else { CP_WAIT(0); }   // x done
        __syncthreads();     // red + x visible

        float mean[2], inv[2];
#pragma unroll
        for (int half = 0; half < 2; half++) {
            const int r = wm2 * 16 + (lane >> 2) + half * 8;
            float S = 0.f, SS = 0.f;
#pragma unroll
            for (int w8 = 0; w8 < 8; w8++) { S += red[r][w8][0]; SS += red[r][w8][1]; }
            const float m = S * (1.0f / NC);
            mean[half] = m;
            inv[half]  = rsqrtf(SS * (1.0f / NC) - m * m + LN_EPS);
        }

#pragma unroll
        for (int ni = 0; ni < 8; ni++) {
            const int col = wn * 64 + ni * 8 + (lane & 3) * 2;
            const float g0 = gbuf[col],       g1 = gbuf[col + 1];
            const float b0 = gbuf[512 + col], b1 = gbuf[512 + col + 1];
#pragma unroll
            for (int half = 0; half < 2; half++) {
                const int rl = wm2 * 16 + (lane >> 2) + half * 8;
                const float2 x2 = *reinterpret_cast<const float2*>(
                    xsf + rl * X_STR + col);
                float2 o;
                o.x = x2.x + ((acc[ni][half * 2]     - mean[half]) * inv[half] * g0 + b0) * sc;
                o.y = x2.y + ((acc[ni][half * 2 + 1] - mean[half]) * inv[half] * g1 + b1) * sc;
                *reinterpret_cast<float2*>(out + (size_t)(row0 + rl) * NC + col) = o;
            }
        }
    }
}

// ---------------------------------------------------------------------------
// Launch. Inputs: 0:x 1:w_f 2:w_h 3:w_fgh 4:gamma_f 5:beta_f 6:gamma_h
// 7:beta_h 8:gamma_fgh 9:beta_fgh 10:scale
// ---------------------------------------------------------------------------
extern "C" void kernel_launch(void* const* d_in, const int* in_sizes, int n_in,
                              void* d_out, int out_size)
{
    (void)in_sizes; (void)n_in; (void)out_size;
    const float* x         = (const float*)d_in[0];
    const float* w_f       = (const float*)d_in[1];
    const float* w_h       = (const float*)d_in[2];
    const float* w_fgh     = (const float*)d_in[3];
    const float* gamma_f   = (const float*)d_in[4];
    const float* beta_f    = (const float*)d_in[5];
    const float* gamma_h   = (const float*)d_in[6];
    const float* beta_h    = (const float*)d_in[7];
    const float* gamma_fgh = (const float*)d_in[8];
    const float* beta_fgh  = (const float*)d_in[9];
    const float* scale     = (const float*)d_in[10];
    float* out             = (float*)d_out;

    cudaFuncSetAttribute(k1_mma, cudaFuncAttributeMaxDynamicSharedMemorySize, K1_SMEM);
    cudaFuncSetAttribute(k3_mma, cudaFuncAttributeMaxDynamicSharedMemorySize, K3_SMEM);

    k0_prep<<<384, 256>>>(w_f, w_h, w_fgh);
    k1_mma<<<NROWS / 128, 512, K1_SMEM>>>(x, gamma_f, beta_f, gamma_h, beta_h);
    k2_softmax<<<NB * NW, 1024>>>();
    k3_mma<<<K3_GRID, 512, K3_SMEM>>>(gamma_fgh, beta_fgh, scale, x, out);
}